// round 3
// baseline (speedup 1.0000x reference)
#include <cuda_runtime.h>
#include <math.h>

// Problem constants (fixed by the dataset)
#define NN 50000
#define EE 800000
#define GGRP 50
#define EPS 1e-5f

// ---------------- scratch (static device memory; no allocation allowed) -------------
// IMPORTANT: these are referenced ONLY from device code. Passing a __device__
// symbol as a host-side kernel argument yields the host shadow address (garbage
// on device) — that was the Round-2 crash.
__device__ __align__(256) float g_featA[NN * 512];   // layer input / GAT output
__device__ __align__(256) float g_featB[NN * 512];   // GEMM output (h = x @ W)
__device__ __align__(256) float g_al[NN * 8];
__device__ __align__(256) float g_ar[NN * 8];
__device__ int   g_deg[NN];
__device__ int   g_rowptr[NN + 1];
__device__ int   g_cursor[NN];
__device__ int   g_csrsrc[EE];
__device__ __align__(256) float g_pool[GGRP * 16];
__device__ float g_cnt[GGRP];

__device__ __forceinline__ float leaky02(float x) { return x > 0.f ? x : 0.2f * x; }

// ---------------- utility kernels ----------------
__global__ void k_init(int n) {
    int i = blockIdx.x * blockDim.x + threadIdx.x;
    if (i < n) { g_deg[i] = 0; g_cursor[i] = 0; }
    if (i < GGRP * 16) g_pool[i] = 0.f;
    if (i < GGRP) g_cnt[i] = 0.f;
}

__global__ void k_gather_emb(const int* __restrict__ x, const float* __restrict__ emb, int n) {
    int i = blockIdx.x * blockDim.x + threadIdx.x;
    if (i < n * 16) {
        int node = i >> 4, c = i & 15;
        g_featA[i] = emb[x[node] * 16 + c];
    }
}

// ---------------- CSR build (edges grouped by dst) ----------------
__global__ void k_count(const int* __restrict__ dst, int e) {
    int i = blockIdx.x * blockDim.x + threadIdx.x;
    if (i < e) atomicAdd(&g_deg[dst[i]], 1);
}

// single-block exclusive scan of g_deg -> g_rowptr (warp-shuffle based)
__global__ void k_scan(int n) {
    __shared__ int warpsum[32];
    __shared__ int carry;
    int tid = threadIdx.x;
    int lane = tid & 31, w = tid >> 5;
    if (tid == 0) carry = 0;
    __syncthreads();
    for (int base = 0; base < n; base += 1024) {
        int v = (base + tid < n) ? g_deg[base + tid] : 0;
        int incl = v;
        #pragma unroll
        for (int o = 1; o < 32; o <<= 1) {
            int t = __shfl_up_sync(0xffffffffu, incl, o);
            if (lane >= o) incl += t;
        }
        if (lane == 31) warpsum[w] = incl;
        __syncthreads();
        if (w == 0) {
            int s = warpsum[lane];
            int si = s;
            #pragma unroll
            for (int o = 1; o < 32; o <<= 1) {
                int t = __shfl_up_sync(0xffffffffu, si, o);
                if (lane >= o) si += t;
            }
            warpsum[lane] = si - s;  // exclusive warp prefix
        }
        __syncthreads();
        int c = carry;
        int excl = warpsum[w] + incl - v + c;
        if (base + tid < n) g_rowptr[base + tid] = excl;
        __syncthreads();
        if (tid == 1023) carry = c + warpsum[31] + incl;
        __syncthreads();
    }
    if (tid == 0) g_rowptr[n] = carry;
}

__global__ void k_scatter(const int* __restrict__ src, const int* __restrict__ dst, int e) {
    int i = blockIdx.x * blockDim.x + threadIdx.x;
    if (i < e) {
        int d = dst[i];
        int pos = g_rowptr[d] + atomicAdd(&g_cursor[d], 1);
        g_csrsrc[pos] = src[i];
    }
}

// ---------------- SGEMM: g_featB = g_featA @ W (row-major) ----------------
// 64x64 tile, BK=16, 256 threads, 4x4 micro-tile.
__global__ __launch_bounds__(256) void k_sgemm_AB(const float* __restrict__ W, int M, int Nc, int K) {
    __shared__ float As[16][64];
    __shared__ float Bs[16][64];
    const float* A = g_featA;
    float* C = g_featB;
    int tid = threadIdx.x;
    int tx = tid & 15, ty = tid >> 4;
    int rowBase = blockIdx.x * 64;
    int colBase = blockIdx.y * 64;
    float acc[4][4] = {};
    for (int k0 = 0; k0 < K; k0 += 16) {
        {
            int r = tid >> 2, c4 = (tid & 3) << 2;
            int row = rowBase + r;
            float4 v = make_float4(0.f, 0.f, 0.f, 0.f);
            if (row < M) v = *(const float4*)(A + (size_t)row * K + k0 + c4);
            As[c4 + 0][r] = v.x; As[c4 + 1][r] = v.y;
            As[c4 + 2][r] = v.z; As[c4 + 3][r] = v.w;
        }
        {
            int k = tid >> 4, c4 = (tid & 15) << 2;
            int col = colBase + c4;
            float4 v = make_float4(0.f, 0.f, 0.f, 0.f);
            if (col < Nc) v = *(const float4*)(W + (size_t)(k0 + k) * Nc + col);
            *(float4*)&Bs[k][c4] = v;
        }
        __syncthreads();
        #pragma unroll
        for (int k = 0; k < 16; k++) {
            float a[4], b[4];
            #pragma unroll
            for (int i = 0; i < 4; i++) a[i] = As[k][ty * 4 + i];
            #pragma unroll
            for (int j = 0; j < 4; j++) b[j] = Bs[k][tx * 4 + j];
            #pragma unroll
            for (int i = 0; i < 4; i++)
                #pragma unroll
                for (int j = 0; j < 4; j++) acc[i][j] += a[i] * b[j];
        }
        __syncthreads();
    }
    #pragma unroll
    for (int i = 0; i < 4; i++) {
        int row = rowBase + ty * 4 + i;
        if (row < M) {
            #pragma unroll
            for (int j = 0; j < 4; j++) {
                int col = colBase + tx * 4 + j;
                if (col < Nc) C[(size_t)row * Nc + col] = acc[i][j];
            }
        }
    }
}

// ---------------- attention coefficients: al/ar per (node, head) ----------------
// reads g_featB (device symbol, referenced in device code only)
template <int H, int C>
__global__ void k_coef(const float* __restrict__ a_src, const float* __restrict__ a_dst, int n) {
    int gw = (blockIdx.x * blockDim.x + threadIdx.x) >> 5;
    int lane = threadIdx.x & 31;
    if (gw >= n * H) return;
    int node = gw / H, h = gw % H;
    const float* f = g_featB + (size_t)node * (H * C) + h * C;
    float sa = 0.f, sd = 0.f;
    #pragma unroll
    for (int c = lane; c < C; c += 32) {
        float v = f[c];
        sa += v * a_src[h * C + c];
        sd += v * a_dst[h * C + c];
    }
    #pragma unroll
    for (int o = 16; o; o >>= 1) {
        sa += __shfl_xor_sync(0xffffffffu, sa, o);
        sd += __shfl_xor_sync(0xffffffffu, sd, o);
    }
    if (lane == 0) { g_al[node * H + h] = sa; g_ar[node * H + h] = sd; }
}

// ---------------- GAT aggregation for HC=512 layers, fused bias+LN+ELU ----------------
// warp per dst node; two-pass segment softmax over incoming edges (+ implicit self-loop)
// reads g_featB, writes g_featA
template <int H, int C>
__global__ __launch_bounds__(256) void k_agg512(const float* __restrict__ bias,
                                                const float* __restrict__ gamma,
                                                const float* __restrict__ beta,
                                                int n) {
    constexpr int HC = H * C;  // 512
    int warp = (blockIdx.x * blockDim.x + threadIdx.x) >> 5;
    int lane = threadIdx.x & 31;
    if (warp >= n) return;
    int node = warp;
    const float* feat = g_featB;
    float* out = g_featA;

    int hj[4];
    #pragma unroll
    for (int j = 0; j < 4; j++) hj[j] = (4 * lane + 128 * j) / C;

    float arv = 0.f, alself = 0.f;
    if (lane < H) {
        arv = g_ar[node * H + lane];
        alself = g_al[node * H + lane];
    }
    float m = -3.4e38f;
    if (lane < H) m = leaky02(alself + arv);

    int beg = g_rowptr[node], end = g_rowptr[node + 1];
    // pass 1: per-head max
    for (int k = beg; k < end; k++) {
        int s = g_csrsrc[k];
        float a = (lane < H) ? g_al[s * H + lane] : 0.f;
        float e = leaky02(a + arv);
        if (lane < H) m = fmaxf(m, e);
    }

    // pass 2: sum of exp + weighted feature accumulation (self-loop first)
    float ssum = 0.f;
    float4 acc[4];
    #pragma unroll
    for (int j = 0; j < 4; j++) acc[j] = make_float4(0.f, 0.f, 0.f, 0.f);

    {
        float ex = (lane < H) ? __expf(leaky02(alself + arv) - m) : 0.f;
        ssum += ex;
        const float4* fp = (const float4*)(feat + (size_t)node * HC);
        #pragma unroll
        for (int j = 0; j < 4; j++) {
            float ev = __shfl_sync(0xffffffffu, ex, hj[j]);
            float4 v = fp[lane + 32 * j];
            acc[j].x += ev * v.x; acc[j].y += ev * v.y;
            acc[j].z += ev * v.z; acc[j].w += ev * v.w;
        }
    }
    for (int k = beg; k < end; k++) {
        int s = g_csrsrc[k];
        float a = (lane < H) ? g_al[s * H + lane] : 0.f;
        float ex = (lane < H) ? __expf(leaky02(a + arv) - m) : 0.f;
        ssum += ex;
        const float4* fp = (const float4*)(feat + (size_t)s * HC);
        #pragma unroll
        for (int j = 0; j < 4; j++) {
            float ev = __shfl_sync(0xffffffffu, ex, hj[j]);
            float4 v = fp[lane + 32 * j];
            acc[j].x += ev * v.x; acc[j].y += ev * v.y;
            acc[j].z += ev * v.z; acc[j].w += ev * v.w;
        }
    }

    float inv = (lane < H) ? 1.f / ssum : 0.f;
    float vals[16];
    float lsum = 0.f;
    #pragma unroll
    for (int j = 0; j < 4; j++) {
        float iv = __shfl_sync(0xffffffffu, inv, hj[j]);
        float4 b4 = ((const float4*)bias)[lane + 32 * j];
        vals[j * 4 + 0] = acc[j].x * iv + b4.x;
        vals[j * 4 + 1] = acc[j].y * iv + b4.y;
        vals[j * 4 + 2] = acc[j].z * iv + b4.z;
        vals[j * 4 + 3] = acc[j].w * iv + b4.w;
        lsum += vals[j * 4 + 0] + vals[j * 4 + 1] + vals[j * 4 + 2] + vals[j * 4 + 3];
    }
    #pragma unroll
    for (int o = 16; o; o >>= 1) lsum += __shfl_xor_sync(0xffffffffu, lsum, o);
    float mean = lsum * (1.f / HC);
    float lvar = 0.f;
    #pragma unroll
    for (int t = 0; t < 16; t++) { float d = vals[t] - mean; lvar += d * d; }
    #pragma unroll
    for (int o = 16; o; o >>= 1) lvar += __shfl_xor_sync(0xffffffffu, lvar, o);
    float rstd = rsqrtf(lvar * (1.f / HC) + EPS);

    float4* op = (float4*)(out + (size_t)node * HC);
    #pragma unroll
    for (int j = 0; j < 4; j++) {
        float4 gg = ((const float4*)gamma)[lane + 32 * j];
        float4 bb = ((const float4*)beta)[lane + 32 * j];
        float4 o4;
        float v;
        v = (vals[j * 4 + 0] - mean) * rstd * gg.x + bb.x; o4.x = v > 0.f ? v : __expf(v) - 1.f;
        v = (vals[j * 4 + 1] - mean) * rstd * gg.y + bb.y; o4.y = v > 0.f ? v : __expf(v) - 1.f;
        v = (vals[j * 4 + 2] - mean) * rstd * gg.z + bb.z; o4.z = v > 0.f ? v : __expf(v) - 1.f;
        v = (vals[j * 4 + 3] - mean) * rstd * gg.w + bb.w; o4.w = v > 0.f ? v : __expf(v) - 1.f;
        op[lane + 32 * j] = o4;
    }
}

// ---------------- layer-3 aggregation (H=1, C=16), fused bias+LN+ELU+pool ----------------
// reads g_featB
__global__ __launch_bounds__(256) void k_agg3(const float* __restrict__ b3,
                                              const float* __restrict__ g3,
                                              const float* __restrict__ be3,
                                              const int* __restrict__ batch, int n) {
    int warp = (blockIdx.x * blockDim.x + threadIdx.x) >> 5;
    int lane = threadIdx.x & 31;
    if (warp >= n) return;
    int node = warp;
    const float* feat = g_featB;

    float arv = g_ar[node];
    float alself = g_al[node];
    float m = leaky02(alself + arv);
    int beg = g_rowptr[node], end = g_rowptr[node + 1];
    for (int k = beg; k < end; k++) {
        int s = g_csrsrc[k];
        m = fmaxf(m, leaky02(g_al[s] + arv));  // uniform across warp (broadcast load)
    }
    float ssum = __expf(leaky02(alself + arv) - m);
    float acc = (lane < 16) ? ssum * feat[(size_t)node * 16 + lane] : 0.f;
    for (int k = beg; k < end; k++) {
        int s = g_csrsrc[k];
        float ex = __expf(leaky02(g_al[s] + arv) - m);
        ssum += ex;
        if (lane < 16) acc += ex * feat[(size_t)s * 16 + lane];
    }
    if (lane < 16) {
        float val = acc / ssum + b3[lane];
        float t = val;
        #pragma unroll
        for (int o = 8; o; o >>= 1) t += __shfl_xor_sync(0x0000ffffu, t, o);
        float mean = t * (1.f / 16.f);
        float d = val - mean;
        float v2 = d * d;
        #pragma unroll
        for (int o = 8; o; o >>= 1) v2 += __shfl_xor_sync(0x0000ffffu, v2, o);
        float rstd = rsqrtf(v2 * (1.f / 16.f) + EPS);
        float o_ = d * rstd * g3[lane] + be3[lane];
        o_ = o_ > 0.f ? o_ : __expf(o_) - 1.f;
        int g = batch[node];
        atomicAdd(&g_pool[g * 16 + lane], o_);
        if (lane == 0) atomicAdd(&g_cnt[g], 1.f);
    }
}

// ---------------- final mean-pool + MLP ----------------
__global__ void k_final(const float* __restrict__ fcW1, const float* __restrict__ fcb1,
                        const float* __restrict__ fcW2, const float* __restrict__ fcb2,
                        float* __restrict__ out) {
    __shared__ float pooled[GGRP][16];
    __shared__ float hid[GGRP][16];
    int t = threadIdx.x;
    if (t < GGRP * 16) {
        int g = t >> 4, c = t & 15;
        pooled[g][c] = g_pool[g * 16 + c] / fmaxf(g_cnt[g], 1.f);
    }
    __syncthreads();
    if (t < GGRP * 16) {
        int g = t >> 4, i = t & 15;
        float s = fcb1[i];
        #pragma unroll
        for (int j = 0; j < 16; j++) s += pooled[g][j] * fcW1[j * 16 + i];
        hid[g][i] = fmaxf(s, 0.f);
    }
    __syncthreads();
    if (t < GGRP * 8) {
        int g = t >> 3, k = t & 7;
        float s = fcb2[k];
        #pragma unroll
        for (int j = 0; j < 16; j++) s += hid[g][j] * fcW2[j * 8 + k];
        out[g * 8 + k] = s;
    }
}

// ---------------- launch ----------------
extern "C" void kernel_launch(void* const* d_in, const int* in_sizes, int n_in,
                              void* d_out, int out_size) {
    const int*   x      = (const int*)d_in[0];
    const int*   ei     = (const int*)d_in[1];
    const int*   batch  = (const int*)d_in[2];
    const float* emb    = (const float*)d_in[3];
    const float* W1     = (const float*)d_in[4];
    const float* a_src1 = (const float*)d_in[5];
    const float* a_dst1 = (const float*)d_in[6];
    const float* b1     = (const float*)d_in[7];
    const float* g1     = (const float*)d_in[8];
    const float* be1    = (const float*)d_in[9];
    const float* W2     = (const float*)d_in[10];
    const float* a_src2 = (const float*)d_in[11];
    const float* a_dst2 = (const float*)d_in[12];
    const float* b2     = (const float*)d_in[13];
    const float* g2     = (const float*)d_in[14];
    const float* be2    = (const float*)d_in[15];
    const float* W3     = (const float*)d_in[16];
    const float* a_src3 = (const float*)d_in[17];
    const float* a_dst3 = (const float*)d_in[18];
    const float* b3     = (const float*)d_in[19];
    const float* g3     = (const float*)d_in[20];
    const float* be3    = (const float*)d_in[21];
    const float* fcW1   = (const float*)d_in[22];
    const float* fcb1   = (const float*)d_in[23];
    const float* fcW2   = (const float*)d_in[24];
    const float* fcb2   = (const float*)d_in[25];

    int n = in_sizes[0];
    int e = in_sizes[1] / 2;
    const int* src = ei;
    const int* dst = ei + e;

    // init + CSR build
    k_init<<<(n + 255) / 256, 256>>>(n);
    k_gather_emb<<<(n * 16 + 255) / 256, 256>>>(x, emb, n);
    k_count<<<(e + 255) / 256, 256>>>(dst, e);
    k_scan<<<1, 1024>>>(n);
    k_scatter<<<(e + 255) / 256, 256>>>(src, dst, e);

    int aggBlocks = (n * 32 + 255) / 256;

    // layer 1: 16 -> 512 (H=8, C=64)
    {
        dim3 grid((n + 63) / 64, 512 / 64);
        k_sgemm_AB<<<grid, 256>>>(W1, n, 512, 16);
        k_coef<8, 64><<<(n * 8 * 32 + 255) / 256, 256>>>(a_src1, a_dst1, n);
        k_agg512<8, 64><<<aggBlocks, 256>>>(b1, g1, be1, n);
    }
    // layer 2: 512 -> 512 (H=4, C=128)
    {
        dim3 grid((n + 63) / 64, 512 / 64);
        k_sgemm_AB<<<grid, 256>>>(W2, n, 512, 512);
        k_coef<4, 128><<<(n * 4 * 32 + 255) / 256, 256>>>(a_src2, a_dst2, n);
        k_agg512<4, 128><<<aggBlocks, 256>>>(b2, g2, be2, n);
    }
    // layer 3: 512 -> 16 (H=1, C=16)
    {
        dim3 grid((n + 63) / 64, 1);
        k_sgemm_AB<<<grid, 256>>>(W3, n, 16, 512);
        k_coef<1, 16><<<(n * 32 + 255) / 256, 256>>>(a_src3, a_dst3, n);
        k_agg3<<<aggBlocks, 256>>>(b3, g3, be3, batch, n);
    }
    // pool + MLP
    k_final<<<1, 800>>>(fcW1, fcb1, fcW2, fcb2, (float*)d_out);
}

// round 7
// speedup vs baseline: 1.2117x; 1.2117x over previous
#include <cuda_runtime.h>
#include <math.h>
#include <stdint.h>

// Problem constants (fixed by the dataset)
#define NN 50000
#define EE 800000
#define GGRP 50
#define TILE 32
#define EPS 1e-5f

// ---------------- scratch (static device memory; no allocation allowed) -------------
// Referenced ONLY from device code (host-side __device__ symbol decay was the R2 crash).
__device__ __align__(256) float g_featA[NN * 512];   // layer input / GAT output
__device__ __align__(256) float g_featB[NN * 512];   // GEMM output (h = x @ W)
__device__ __align__(256) float g_al[NN * 8];
__device__ __align__(256) float g_ar[NN * 8];
__device__ __align__(256) float g_tab[TILE * 512];   // layer-1 lookup table emb @ W1
__device__ float g_tabal[TILE * 8];
__device__ float g_tabar[TILE * 8];
__device__ int   g_deg[NN];
__device__ int   g_rowptr[NN + 1];
__device__ int   g_cursor[NN];
__device__ int   g_csrsrc[EE];
__device__ __align__(256) float g_pool[GGRP * 16];
__device__ float g_cnt[GGRP];

__device__ __forceinline__ float leaky02(float x) { return x > 0.f ? x : 0.2f * x; }

// ---------------- utility kernels ----------------
__global__ void k_init(int n) {
    int i = blockIdx.x * blockDim.x + threadIdx.x;
    if (i < n) { g_deg[i] = 0; g_cursor[i] = 0; }
    if (i < GGRP * 16) g_pool[i] = 0.f;
    if (i < GGRP) g_cnt[i] = 0.f;
}

// ---------------- CSR build (edges grouped by dst) ----------------
__global__ void k_count(const int* __restrict__ dst, int e) {
    int i = blockIdx.x * blockDim.x + threadIdx.x;
    if (i < e) atomicAdd(&g_deg[dst[i]], 1);
}

// single-block exclusive scan of g_deg -> g_rowptr, 4 elements/thread (int4)
__global__ void k_scan(int n) {
    __shared__ int warpsum[32];
    __shared__ int carry;
    int tid = threadIdx.x;
    int lane = tid & 31, w = tid >> 5;
    if (tid == 0) carry = 0;
    __syncthreads();
    for (int base = 0; base < n; base += 4096) {
        int idx = base + tid * 4;
        int v0 = 0, v1 = 0, v2 = 0, v3 = 0;
        if (idx + 3 < n) {
            int4 t4 = *(const int4*)&g_deg[idx];
            v0 = t4.x; v1 = t4.y; v2 = t4.z; v3 = t4.w;
        } else {
            if (idx     < n) v0 = g_deg[idx];
            if (idx + 1 < n) v1 = g_deg[idx + 1];
            if (idx + 2 < n) v2 = g_deg[idx + 2];
            if (idx + 3 < n) v3 = g_deg[idx + 3];
        }
        int s0 = v0, s1 = s0 + v1, s2 = s1 + v2, s3 = s2 + v3;  // local inclusive
        int incl = s3;
        #pragma unroll
        for (int o = 1; o < 32; o <<= 1) {
            int t = __shfl_up_sync(0xffffffffu, incl, o);
            if (lane >= o) incl += t;
        }
        if (lane == 31) warpsum[w] = incl;
        __syncthreads();
        if (w == 0) {
            int s = warpsum[lane];
            int si = s;
            #pragma unroll
            for (int o = 1; o < 32; o <<= 1) {
                int t = __shfl_up_sync(0xffffffffu, si, o);
                if (lane >= o) si += t;
            }
            warpsum[lane] = si - s;  // exclusive warp prefix
        }
        __syncthreads();
        int c = carry;
        int excl = warpsum[w] + (incl - s3) + c;  // exclusive start for this thread's 4
        if (idx     < n) g_rowptr[idx]     = excl;
        if (idx + 1 < n) g_rowptr[idx + 1] = excl + s0;
        if (idx + 2 < n) g_rowptr[idx + 2] = excl + s1;
        if (idx + 3 < n) g_rowptr[idx + 3] = excl + s2;
        __syncthreads();
        if (tid == 1023) carry = c + warpsum[31] + incl;
        __syncthreads();
    }
    if (tid == 0) g_rowptr[n] = carry;
}

__global__ void k_scatter(const int* __restrict__ src, const int* __restrict__ dst, int e) {
    int i = blockIdx.x * blockDim.x + threadIdx.x;
    if (i < e) {
        int d = dst[i];
        int pos = g_rowptr[d] + atomicAdd(&g_cursor[d], 1);
        g_csrsrc[pos] = src[i];
    }
}

// ---------------- layer-1 table: g_tab[32,512] = emb[32,16] @ W1[16,512] --------------
__global__ void k_table(const float* __restrict__ emb, const float* __restrict__ W1) {
    int c = threadIdx.x;   // 512
    int r = blockIdx.x;    // 32
    float s = 0.f;
    #pragma unroll
    for (int k = 0; k < 16; k++) s += emb[r * 16 + k] * W1[k * 512 + c];
    g_tab[r * 512 + c] = s;
}

// al/ar for the 32 table rows (H=8, C=64): block per row, warp per head
__global__ void k_tabcoef(const float* __restrict__ a_src, const float* __restrict__ a_dst) {
    int r = blockIdx.x;              // 32
    int h = threadIdx.x >> 5;        // 8 warps
    int lane = threadIdx.x & 31;
    const float* f = g_tab + r * 512 + h * 64;
    float sa = 0.f, sd = 0.f;
    #pragma unroll
    for (int c = lane; c < 64; c += 32) {
        float v = f[c];
        sa += v * a_src[h * 64 + c];
        sd += v * a_dst[h * 64 + c];
    }
    #pragma unroll
    for (int o = 16; o; o >>= 1) {
        sa += __shfl_xor_sync(0xffffffffu, sa, o);
        sd += __shfl_xor_sync(0xffffffffu, sd, o);
    }
    if (lane == 0) { g_tabal[r * 8 + h] = sa; g_tabar[r * 8 + h] = sd; }
}

// gather layer-1 features: g_featB[i] = g_tab[x[i]]  (float4 per thread)
__global__ void k_gather1(const int* __restrict__ x, int n) {
    int i = blockIdx.x * blockDim.x + threadIdx.x;
    int node = i >> 7, c = i & 127;      // 128 float4 per node
    if (node < n)
        ((float4*)g_featB)[(size_t)node * 128 + c] =
            ((const float4*)g_tab)[x[node] * 128 + c];
}

// gather layer-1 attention coefficients
__global__ void k_gathercoef1(const int* __restrict__ x, int n) {
    int i = blockIdx.x * blockDim.x + threadIdx.x;
    if (i < n * 8) {
        int node = i >> 3, h = i & 7;
        int r = x[node];
        g_al[i] = g_tabal[r * 8 + h];
        g_ar[i] = g_tabar[r * 8 + h];
    }
}

// ---------------- fp32 SGEMM (layer 3): g_featB = g_featA @ W ----------------
__global__ __launch_bounds__(256) void k_sgemm_AB(const float* __restrict__ W, int M, int Nc, int K) {
    __shared__ float As[16][64];
    __shared__ float Bs[16][64];
    const float* A = g_featA;
    float* C = g_featB;
    int tid = threadIdx.x;
    int tx = tid & 15, ty = tid >> 4;
    int rowBase = blockIdx.x * 64;
    int colBase = blockIdx.y * 64;
    float acc[4][4] = {};
    for (int k0 = 0; k0 < K; k0 += 16) {
        {
            int r = tid >> 2, c4 = (tid & 3) << 2;
            int row = rowBase + r;
            float4 v = make_float4(0.f, 0.f, 0.f, 0.f);
            if (row < M) v = *(const float4*)(A + (size_t)row * K + k0 + c4);
            As[c4 + 0][r] = v.x; As[c4 + 1][r] = v.y;
            As[c4 + 2][r] = v.z; As[c4 + 3][r] = v.w;
        }
        {
            int k = tid >> 4, c4 = (tid & 15) << 2;
            int col = colBase + c4;
            float4 v = make_float4(0.f, 0.f, 0.f, 0.f);
            if (col < Nc) v = *(const float4*)(W + (size_t)(k0 + k) * Nc + col);
            *(float4*)&Bs[k][c4] = v;
        }
        __syncthreads();
        #pragma unroll
        for (int k = 0; k < 16; k++) {
            float a[4], b[4];
            #pragma unroll
            for (int i = 0; i < 4; i++) a[i] = As[k][ty * 4 + i];
            #pragma unroll
            for (int j = 0; j < 4; j++) b[j] = Bs[k][tx * 4 + j];
            #pragma unroll
            for (int i = 0; i < 4; i++)
                #pragma unroll
                for (int j = 0; j < 4; j++) acc[i][j] += a[i] * b[j];
        }
        __syncthreads();
    }
    #pragma unroll
    for (int i = 0; i < 4; i++) {
        int row = rowBase + ty * 4 + i;
        if (row < M) {
            #pragma unroll
            for (int j = 0; j < 4; j++) {
                int col = colBase + tx * 4 + j;
                if (col < Nc) C[(size_t)row * Nc + col] = acc[i][j];
            }
        }
    }
}

// ---------------- tf32 tensor-core GEMM (layer 2): g_featB = g_featA[M,512] @ W[512,512] ----
// Block tile 128x64, K-chunk 32. 8 warps, each 32x32 via mma.sync.m16n8k8 tf32.
// A/B staged into smem in FRAGMENT-MAJOR layout so mainloop fragment loads are
// a single LDS.128 (A) / LDS.64 (B) per tile — no ldmatrix needed.
__global__ __launch_bounds__(256) void k_mma_tf32(const float* __restrict__ W, int M) {
    __shared__ uint32_t Af[4 * 8 * 32 * 4];  // [kb][mt][thread][idx]  16KB
    __shared__ uint32_t Bf[4 * 8 * 32 * 2];  // [kb][nt][thread][idx]   8KB
    const float* A = g_featA;
    float* C = g_featB;
    int tid = threadIdx.x;
    int lane = tid & 31, wid = tid >> 5;
    int warpM = wid & 3, warpN = wid >> 2;     // 4 x 2 warp grid
    int rowBase = blockIdx.x * 128;
    int colBase = blockIdx.y * 64;

    float acc[2][4][4];
    #pragma unroll
    for (int i = 0; i < 2; i++)
        #pragma unroll
        for (int j = 0; j < 4; j++)
            #pragma unroll
            for (int q = 0; q < 4; q++) acc[i][j][q] = 0.f;

    for (int k0 = 0; k0 < 512; k0 += 32) {
        // ---- stage A tile (128 x 32) into fragment-major smem ----
        #pragma unroll
        for (int p = 0; p < 4; p++) {
            int r = p * 32 + (tid >> 3);
            int f = tid & 7;
            int row = rowBase + r;
            float4 v = make_float4(0.f, 0.f, 0.f, 0.f);
            if (row < M) v = *(const float4*)(A + (size_t)row * 512 + k0 + f * 4);
            int mt = r >> 4, rr = r & 15, g = rr & 7, half = rr >> 3;
            float vv[4] = {v.x, v.y, v.z, v.w};
            #pragma unroll
            for (int e = 0; e < 4; e++) {
                int kin = f * 4 + e;
                int tg = kin & 3, khalf = (kin >> 2) & 1, kb = kin >> 3;
                uint32_t tf;
                asm("cvt.rna.tf32.f32 %0, %1;" : "=r"(tf) : "f"(vv[e]));
                Af[(((kb * 8 + mt) * 32) + (g * 4 + tg)) * 4 + khalf * 2 + half] = tf;
            }
        }
        // ---- stage B tile (32 x 64) ----
        #pragma unroll
        for (int p = 0; p < 2; p++) {
            int kr = p * 16 + (tid >> 4);
            int nc4 = tid & 15;
            float4 v = *(const float4*)(W + (size_t)(k0 + kr) * 512 + colBase + nc4 * 4);
            int tg = kr & 3, khalf = (kr >> 2) & 1, kb = kr >> 3;
            float vv[4] = {v.x, v.y, v.z, v.w};
            #pragma unroll
            for (int e = 0; e < 4; e++) {
                int nn = nc4 * 4 + e;
                int nt = nn >> 3, g = nn & 7;
                uint32_t tf;
                asm("cvt.rna.tf32.f32 %0, %1;" : "=r"(tf) : "f"(vv[e]));
                Bf[(((kb * 8 + nt) * 32) + (g * 4 + tg)) * 2 + khalf] = tf;
            }
        }
        __syncthreads();
        // ---- 4 k-steps of m16n8k8 ----
        #pragma unroll
        for (int kb = 0; kb < 4; kb++) {
            uint32_t a[2][4], b[4][2];
            #pragma unroll
            for (int mt2 = 0; mt2 < 2; mt2++) {
                int mt = warpM * 2 + mt2;
                uint4 aa = *(const uint4*)&Af[((kb * 8 + mt) * 32 + lane) * 4];
                a[mt2][0] = aa.x; a[mt2][1] = aa.y; a[mt2][2] = aa.z; a[mt2][3] = aa.w;
            }
            #pragma unroll
            for (int nt2 = 0; nt2 < 4; nt2++) {
                int nt = warpN * 4 + nt2;
                uint2 bb = *(const uint2*)&Bf[((kb * 8 + nt) * 32 + lane) * 2];
                b[nt2][0] = bb.x; b[nt2][1] = bb.y;
            }
            #pragma unroll
            for (int mt2 = 0; mt2 < 2; mt2++)
                #pragma unroll
                for (int nt2 = 0; nt2 < 4; nt2++)
                    asm volatile(
                        "mma.sync.aligned.m16n8k8.row.col.f32.tf32.tf32.f32 "
                        "{%0,%1,%2,%3}, {%4,%5,%6,%7}, {%8,%9}, {%0,%1,%2,%3};"
                        : "+f"(acc[mt2][nt2][0]), "+f"(acc[mt2][nt2][1]),
                          "+f"(acc[mt2][nt2][2]), "+f"(acc[mt2][nt2][3])
                        : "r"(a[mt2][0]), "r"(a[mt2][1]), "r"(a[mt2][2]), "r"(a[mt2][3]),
                          "r"(b[nt2][0]), "r"(b[nt2][1]));
        }
        __syncthreads();
    }
    // ---- epilogue ----
    int g = lane >> 2, tg = lane & 3;
    #pragma unroll
    for (int mt2 = 0; mt2 < 2; mt2++) {
        int row0 = rowBase + warpM * 32 + mt2 * 16 + g;
        #pragma unroll
        for (int nt2 = 0; nt2 < 4; nt2++) {
            int col = colBase + warpN * 32 + nt2 * 8 + tg * 2;
            if (row0 < M)
                *(float2*)(C + (size_t)row0 * 512 + col) =
                    make_float2(acc[mt2][nt2][0], acc[mt2][nt2][1]);
            if (row0 + 8 < M)
                *(float2*)(C + (size_t)(row0 + 8) * 512 + col) =
                    make_float2(acc[mt2][nt2][2], acc[mt2][nt2][3]);
        }
    }
}

// ---------------- attention coefficients: al/ar per (node, head) ----------------
template <int H, int C>
__global__ void k_coef(const float* __restrict__ a_src, const float* __restrict__ a_dst, int n) {
    int gw = (blockIdx.x * blockDim.x + threadIdx.x) >> 5;
    int lane = threadIdx.x & 31;
    if (gw >= n * H) return;
    int node = gw / H, h = gw % H;
    const float* f = g_featB + (size_t)node * (H * C) + h * C;
    float sa = 0.f, sd = 0.f;
    #pragma unroll
    for (int c = lane; c < C; c += 32) {
        float v = f[c];
        sa += v * a_src[h * C + c];
        sd += v * a_dst[h * C + c];
    }
    #pragma unroll
    for (int o = 16; o; o >>= 1) {
        sa += __shfl_xor_sync(0xffffffffu, sa, o);
        sd += __shfl_xor_sync(0xffffffffu, sd, o);
    }
    if (lane == 0) { g_al[node * H + h] = sa; g_ar[node * H + h] = sd; }
}

// ---------------- GAT aggregation for HC=512 layers, fused bias+LN+ELU ----------------
template <int H, int C>
__global__ __launch_bounds__(256) void k_agg512(const float* __restrict__ bias,
                                                const float* __restrict__ gamma,
                                                const float* __restrict__ beta,
                                                int n) {
    constexpr int HC = H * C;  // 512
    int warp = (blockIdx.x * blockDim.x + threadIdx.x) >> 5;
    int lane = threadIdx.x & 31;
    if (warp >= n) return;
    int node = warp;
    const float* feat = g_featB;
    float* out = g_featA;

    int hj[4];
    #pragma unroll
    for (int j = 0; j < 4; j++) hj[j] = (4 * lane + 128 * j) / C;

    float arv = 0.f, alself = 0.f;
    if (lane < H) {
        arv = g_ar[node * H + lane];
        alself = g_al[node * H + lane];
    }
    float m = -3.4e38f;
    if (lane < H) m = leaky02(alself + arv);

    int beg = g_rowptr[node], end = g_rowptr[node + 1];
    for (int k = beg; k < end; k++) {
        int s = g_csrsrc[k];
        float a = (lane < H) ? g_al[s * H + lane] : 0.f;
        float e = leaky02(a + arv);
        if (lane < H) m = fmaxf(m, e);
    }

    float ssum = 0.f;
    float4 acc[4];
    #pragma unroll
    for (int j = 0; j < 4; j++) acc[j] = make_float4(0.f, 0.f, 0.f, 0.f);

    {
        float ex = (lane < H) ? __expf(leaky02(alself + arv) - m) : 0.f;
        ssum += ex;
        const float4* fp = (const float4*)(feat + (size_t)node * HC);
        #pragma unroll
        for (int j = 0; j < 4; j++) {
            float ev = __shfl_sync(0xffffffffu, ex, hj[j]);
            float4 v = fp[lane + 32 * j];
            acc[j].x += ev * v.x; acc[j].y += ev * v.y;
            acc[j].z += ev * v.z; acc[j].w += ev * v.w;
        }
    }
    for (int k = beg; k < end; k++) {
        int s = g_csrsrc[k];
        float a = (lane < H) ? g_al[s * H + lane] : 0.f;
        float ex = (lane < H) ? __expf(leaky02(a + arv) - m) : 0.f;
        ssum += ex;
        const float4* fp = (const float4*)(feat + (size_t)s * HC);
        #pragma unroll
        for (int j = 0; j < 4; j++) {
            float ev = __shfl_sync(0xffffffffu, ex, hj[j]);
            float4 v = fp[lane + 32 * j];
            acc[j].x += ev * v.x; acc[j].y += ev * v.y;
            acc[j].z += ev * v.z; acc[j].w += ev * v.w;
        }
    }

    float inv = (lane < H) ? 1.f / ssum : 0.f;
    float vals[16];
    float lsum = 0.f;
    #pragma unroll
    for (int j = 0; j < 4; j++) {
        float iv = __shfl_sync(0xffffffffu, inv, hj[j]);
        float4 b4 = ((const float4*)bias)[lane + 32 * j];
        vals[j * 4 + 0] = acc[j].x * iv + b4.x;
        vals[j * 4 + 1] = acc[j].y * iv + b4.y;
        vals[j * 4 + 2] = acc[j].z * iv + b4.z;
        vals[j * 4 + 3] = acc[j].w * iv + b4.w;
        lsum += vals[j * 4 + 0] + vals[j * 4 + 1] + vals[j * 4 + 2] + vals[j * 4 + 3];
    }
    #pragma unroll
    for (int o = 16; o; o >>= 1) lsum += __shfl_xor_sync(0xffffffffu, lsum, o);
    float mean = lsum * (1.f / HC);
    float lvar = 0.f;
    #pragma unroll
    for (int t = 0; t < 16; t++) { float d = vals[t] - mean; lvar += d * d; }
    #pragma unroll
    for (int o = 16; o; o >>= 1) lvar += __shfl_xor_sync(0xffffffffu, lvar, o);
    float rstd = rsqrtf(lvar * (1.f / HC) + EPS);

    float4* op = (float4*)(out + (size_t)node * HC);
    #pragma unroll
    for (int j = 0; j < 4; j++) {
        float4 gg = ((const float4*)gamma)[lane + 32 * j];
        float4 bb = ((const float4*)beta)[lane + 32 * j];
        float4 o4;
        float v;
        v = (vals[j * 4 + 0] - mean) * rstd * gg.x + bb.x; o4.x = v > 0.f ? v : __expf(v) - 1.f;
        v = (vals[j * 4 + 1] - mean) * rstd * gg.y + bb.y; o4.y = v > 0.f ? v : __expf(v) - 1.f;
        v = (vals[j * 4 + 2] - mean) * rstd * gg.z + bb.z; o4.z = v > 0.f ? v : __expf(v) - 1.f;
        v = (vals[j * 4 + 3] - mean) * rstd * gg.w + bb.w; o4.w = v > 0.f ? v : __expf(v) - 1.f;
        op[lane + 32 * j] = o4;
    }
}

// ---------------- layer-3 aggregation (H=1, C=16), fused bias+LN+ELU+pool ----------------
__global__ __launch_bounds__(256) void k_agg3(const float* __restrict__ b3,
                                              const float* __restrict__ g3,
                                              const float* __restrict__ be3,
                                              const int* __restrict__ batch, int n) {
    int warp = (blockIdx.x * blockDim.x + threadIdx.x) >> 5;
    int lane = threadIdx.x & 31;
    if (warp >= n) return;
    int node = warp;
    const float* feat = g_featB;

    float arv = g_ar[node];
    float alself = g_al[node];
    float m = leaky02(alself + arv);
    int beg = g_rowptr[node], end = g_rowptr[node + 1];
    for (int k = beg; k < end; k++) {
        int s = g_csrsrc[k];
        m = fmaxf(m, leaky02(g_al[s] + arv));
    }
    float ssum = __expf(leaky02(alself + arv) - m);
    float acc = (lane < 16) ? ssum * feat[(size_t)node * 16 + lane] : 0.f;
    for (int k = beg; k < end; k++) {
        int s = g_csrsrc[k];
        float ex = __expf(leaky02(g_al[s] + arv) - m);
        ssum += ex;
        if (lane < 16) acc += ex * feat[(size_t)s * 16 + lane];
    }
    if (lane < 16) {
        float val = acc / ssum + b3[lane];
        float t = val;
        #pragma unroll
        for (int o = 8; o; o >>= 1) t += __shfl_xor_sync(0x0000ffffu, t, o);
        float mean = t * (1.f / 16.f);
        float d = val - mean;
        float v2 = d * d;
        #pragma unroll
        for (int o = 8; o; o >>= 1) v2 += __shfl_xor_sync(0x0000ffffu, v2, o);
        float rstd = rsqrtf(v2 * (1.f / 16.f) + EPS);
        float o_ = d * rstd * g3[lane] + be3[lane];
        o_ = o_ > 0.f ? o_ : __expf(o_) - 1.f;
        int g = batch[node];
        atomicAdd(&g_pool[g * 16 + lane], o_);
        if (lane == 0) atomicAdd(&g_cnt[g], 1.f);
    }
}

// ---------------- final mean-pool + MLP ----------------
__global__ void k_final(const float* __restrict__ fcW1, const float* __restrict__ fcb1,
                        const float* __restrict__ fcW2, const float* __restrict__ fcb2,
                        float* __restrict__ out) {
    __shared__ float pooled[GGRP][16];
    __shared__ float hid[GGRP][16];
    int t = threadIdx.x;
    if (t < GGRP * 16) {
        int g = t >> 4, c = t & 15;
        pooled[g][c] = g_pool[g * 16 + c] / fmaxf(g_cnt[g], 1.f);
    }
    __syncthreads();
    if (t < GGRP * 16) {
        int g = t >> 4, i = t & 15;
        float s = fcb1[i];
        #pragma unroll
        for (int j = 0; j < 16; j++) s += pooled[g][j] * fcW1[j * 16 + i];
        hid[g][i] = fmaxf(s, 0.f);
    }
    __syncthreads();
    if (t < GGRP * 8) {
        int g = t >> 3, k = t & 7;
        float s = fcb2[k];
        #pragma unroll
        for (int j = 0; j < 16; j++) s += hid[g][j] * fcW2[j * 8 + k];
        out[g * 8 + k] = s;
    }
}

// ---------------- launch ----------------
extern "C" void kernel_launch(void* const* d_in, const int* in_sizes, int n_in,
                              void* d_out, int out_size) {
    const int*   x      = (const int*)d_in[0];
    const int*   ei     = (const int*)d_in[1];
    const int*   batch  = (const int*)d_in[2];
    const float* emb    = (const float*)d_in[3];
    const float* W1     = (const float*)d_in[4];
    const float* a_src1 = (const float*)d_in[5];
    const float* a_dst1 = (const float*)d_in[6];
    const float* b1     = (const float*)d_in[7];
    const float* g1     = (const float*)d_in[8];
    const float* be1    = (const float*)d_in[9];
    const float* W2     = (const float*)d_in[10];
    const float* a_src2 = (const float*)d_in[11];
    const float* a_dst2 = (const float*)d_in[12];
    const float* b2     = (const float*)d_in[13];
    const float* g2     = (const float*)d_in[14];
    const float* be2    = (const float*)d_in[15];
    const float* W3     = (const float*)d_in[16];
    const float* a_src3 = (const float*)d_in[17];
    const float* a_dst3 = (const float*)d_in[18];
    const float* b3     = (const float*)d_in[19];
    const float* g3     = (const float*)d_in[20];
    const float* be3    = (const float*)d_in[21];
    const float* fcW1   = (const float*)d_in[22];
    const float* fcb1   = (const float*)d_in[23];
    const float* fcW2   = (const float*)d_in[24];
    const float* fcb2   = (const float*)d_in[25];

    int n = in_sizes[0];
    int e = in_sizes[1] / 2;
    const int* src = ei;
    const int* dst = ei + e;

    // init + CSR build
    k_init<<<(n + 255) / 256, 256>>>(n);
    k_count<<<(e + 255) / 256, 256>>>(dst, e);
    k_scan<<<1, 1024>>>(n);
    k_scatter<<<(e + 255) / 256, 256>>>(src, dst, e);

    int aggBlocks = (n * 32 + 255) / 256;

    // layer 1: 16 -> 512 (H=8, C=64). Input has only 32 distinct rows, so the
    // GEMM collapses to a 32x512 table + gather; al/ar likewise 32x8 + gather.
    {
        k_table<<<TILE, 512>>>(emb, W1);
        k_tabcoef<<<TILE, 256>>>(a_src1, a_dst1);
        k_gather1<<<(n * 128 + 255) / 256, 256>>>(x, n);
        k_gathercoef1<<<(n * 8 + 255) / 256, 256>>>(x, n);
        k_agg512<8, 64><<<aggBlocks, 256>>>(b1, g1, be1, n);
    }
    // layer 2: 512 -> 512 (H=4, C=128), tf32 tensor-core GEMM
    {
        dim3 grid((n + 127) / 128, 512 / 64);
        k_mma_tf32<<<grid, 256>>>(W2, n);
        k_coef<4, 128><<<(n * 4 * 32 + 255) / 256, 256>>>(a_src2, a_dst2, n);
        k_agg512<4, 128><<<aggBlocks, 256>>>(b2, g2, be2, n);
    }
    // layer 3: 512 -> 16 (H=1, C=16), fp32 GEMM
    {
        dim3 grid((n + 63) / 64, 1);
        k_sgemm_AB<<<grid, 256>>>(W3, n, 16, 512);
        k_coef<1, 16><<<(n * 32 + 255) / 256, 256>>>(a_src3, a_dst3, n);
        k_agg3<<<aggBlocks, 256>>>(b3, g3, be3, batch, n);
    }
    // pool + MLP
    k_final<<<1, 800>>>(fcW1, fcb1, fcW2, fcb2, (float*)d_out);
}

// round 10
// speedup vs baseline: 1.3891x; 1.1464x over previous
#include <cuda_runtime.h>
#include <math.h>
#include <stdint.h>

// Problem constants (fixed by the dataset)
#define NN 50000
#define EE 800000
#define GGRP 50
#define TILE 32
#define EPS 1e-5f

// ---------------- scratch (static device memory; no allocation allowed) -------------
// Referenced ONLY from device code (host-side __device__ symbol decay was the R2 crash).
__device__ __align__(256) float g_featA[NN * 512];   // layer input / GAT output
__device__ __align__(256) float g_featB[NN * 512];   // GEMM output (h = x @ W)
__device__ __align__(256) float g_al[NN * 8];
__device__ __align__(256) float g_ar[NN * 8];
__device__ __align__(256) float g_tab[TILE * 512];   // layer-1 lookup table emb @ W1
__device__ float g_tabal[TILE * 8];
__device__ float g_tabar[TILE * 8];
__device__ int   g_deg[NN];
__device__ int   g_rowptr[NN + 1];
__device__ int   g_cursor[NN];
__device__ int   g_csrsrc[EE];
__device__ __align__(256) float g_pool[GGRP * 16];
__device__ float g_cnt[GGRP];

__device__ __forceinline__ float leaky02(float x) { return x > 0.f ? x : 0.2f * x; }

// ---------------- utility kernels ----------------
__global__ void k_init(int n) {
    int i = blockIdx.x * blockDim.x + threadIdx.x;
    if (i < n) { g_deg[i] = 0; g_cursor[i] = 0; }
    if (i < GGRP * 16) g_pool[i] = 0.f;
    if (i < GGRP) g_cnt[i] = 0.f;
}

// ---------------- CSR build (edges grouped by dst) ----------------
__global__ void k_count(const int* __restrict__ dst, int e) {
    int i = blockIdx.x * blockDim.x + threadIdx.x;
    if (i < e) atomicAdd(&g_deg[dst[i]], 1);
}

// single-block exclusive scan of g_deg -> g_rowptr, 4 elements/thread (int4)
__global__ void k_scan(int n) {
    __shared__ int warpsum[32];
    __shared__ int carry;
    int tid = threadIdx.x;
    int lane = tid & 31, w = tid >> 5;
    if (tid == 0) carry = 0;
    __syncthreads();
    for (int base = 0; base < n; base += 4096) {
        int idx = base + tid * 4;
        int v0 = 0, v1 = 0, v2 = 0, v3 = 0;
        if (idx + 3 < n) {
            int4 t4 = *(const int4*)&g_deg[idx];
            v0 = t4.x; v1 = t4.y; v2 = t4.z; v3 = t4.w;
        } else {
            if (idx     < n) v0 = g_deg[idx];
            if (idx + 1 < n) v1 = g_deg[idx + 1];
            if (idx + 2 < n) v2 = g_deg[idx + 2];
            if (idx + 3 < n) v3 = g_deg[idx + 3];
        }
        int s0 = v0, s1 = s0 + v1, s2 = s1 + v2, s3 = s2 + v3;  // local inclusive
        int incl = s3;
        #pragma unroll
        for (int o = 1; o < 32; o <<= 1) {
            int t = __shfl_up_sync(0xffffffffu, incl, o);
            if (lane >= o) incl += t;
        }
        if (lane == 31) warpsum[w] = incl;
        __syncthreads();
        if (w == 0) {
            int s = warpsum[lane];
            int si = s;
            #pragma unroll
            for (int o = 1; o < 32; o <<= 1) {
                int t = __shfl_up_sync(0xffffffffu, si, o);
                if (lane >= o) si += t;
            }
            warpsum[lane] = si - s;  // exclusive warp prefix
        }
        __syncthreads();
        int c = carry;
        int excl = warpsum[w] + (incl - s3) + c;  // exclusive start for this thread's 4
        if (idx     < n) g_rowptr[idx]     = excl;
        if (idx + 1 < n) g_rowptr[idx + 1] = excl + s0;
        if (idx + 2 < n) g_rowptr[idx + 2] = excl + s1;
        if (idx + 3 < n) g_rowptr[idx + 3] = excl + s2;
        __syncthreads();
        if (tid == 1023) carry = c + warpsum[31] + incl;
        __syncthreads();
    }
    if (tid == 0) g_rowptr[n] = carry;
}

__global__ void k_scatter(const int* __restrict__ src, const int* __restrict__ dst, int e) {
    int i = blockIdx.x * blockDim.x + threadIdx.x;
    if (i < e) {
        int d = dst[i];
        int pos = g_rowptr[d] + atomicAdd(&g_cursor[d], 1);
        g_csrsrc[pos] = src[i];
    }
}

// ---------------- layer-1 table: g_tab[32,512] = emb[32,16] @ W1[16,512] --------------
__global__ void k_table(const float* __restrict__ emb, const float* __restrict__ W1) {
    int c = threadIdx.x;   // 512
    int r = blockIdx.x;    // 32
    float s = 0.f;
    #pragma unroll
    for (int k = 0; k < 16; k++) s += emb[r * 16 + k] * W1[k * 512 + c];
    g_tab[r * 512 + c] = s;
}

// al/ar for the 32 table rows (H=8, C=64): block per row, warp per head
__global__ void k_tabcoef(const float* __restrict__ a_src, const float* __restrict__ a_dst) {
    int r = blockIdx.x;              // 32
    int h = threadIdx.x >> 5;        // 8 warps
    int lane = threadIdx.x & 31;
    const float* f = g_tab + r * 512 + h * 64;
    float sa = 0.f, sd = 0.f;
    #pragma unroll
    for (int c = lane; c < 64; c += 32) {
        float v = f[c];
        sa += v * a_src[h * 64 + c];
        sd += v * a_dst[h * 64 + c];
    }
    #pragma unroll
    for (int o = 16; o; o >>= 1) {
        sa += __shfl_xor_sync(0xffffffffu, sa, o);
        sd += __shfl_xor_sync(0xffffffffu, sd, o);
    }
    if (lane == 0) { g_tabal[r * 8 + h] = sa; g_tabar[r * 8 + h] = sd; }
}

// ---------------- layer-1 aggregation straight from the 64KB table ----------------
// features/coefs of node i are tab[x[i]] / tabal[x[i]] / tabar[x[i]] — all L1-resident.
// Bit-exact same arithmetic as the generic path. Writes g_featA.
__global__ __launch_bounds__(256) void k_agg1(const int* __restrict__ x,
                                              const float* __restrict__ bias,
                                              const float* __restrict__ gamma,
                                              const float* __restrict__ beta,
                                              int n) {
    constexpr int H = 8, C = 64, HC = 512;
    int warp = (blockIdx.x * blockDim.x + threadIdx.x) >> 5;
    int lane = threadIdx.x & 31;
    if (warp >= n) return;
    int node = warp;
    float* out = g_featA;

    int hj[4];
    #pragma unroll
    for (int j = 0; j < 4; j++) hj[j] = (4 * lane + 128 * j) / C;

    int xr = x[node];
    float arv = 0.f, alself = 0.f;
    if (lane < H) {
        arv = g_tabar[xr * H + lane];
        alself = g_tabal[xr * H + lane];
    }
    float m = -3.4e38f;
    if (lane < H) m = leaky02(alself + arv);

    int beg = g_rowptr[node], end = g_rowptr[node + 1];
    // pass 1: per-head max
    for (int k = beg; k < end; k++) {
        int s = g_csrsrc[k];
        int xs = x[s];
        float a = (lane < H) ? g_tabal[xs * H + lane] : 0.f;
        float e = leaky02(a + arv);
        if (lane < H) m = fmaxf(m, e);
    }

    // pass 2: sum of exp + weighted feature accumulation (self-loop first)
    float ssum = 0.f;
    float4 acc[4];
    #pragma unroll
    for (int j = 0; j < 4; j++) acc[j] = make_float4(0.f, 0.f, 0.f, 0.f);

    {
        float ex = (lane < H) ? __expf(leaky02(alself + arv) - m) : 0.f;
        ssum += ex;
        const float4* fp = (const float4*)(g_tab + xr * HC);
        #pragma unroll
        for (int j = 0; j < 4; j++) {
            float ev = __shfl_sync(0xffffffffu, ex, hj[j]);
            float4 v = fp[lane + 32 * j];
            acc[j].x += ev * v.x; acc[j].y += ev * v.y;
            acc[j].z += ev * v.z; acc[j].w += ev * v.w;
        }
    }
    for (int k = beg; k < end; k++) {
        int s = g_csrsrc[k];
        int xs = x[s];
        float a = (lane < H) ? g_tabal[xs * H + lane] : 0.f;
        float ex = (lane < H) ? __expf(leaky02(a + arv) - m) : 0.f;
        ssum += ex;
        const float4* fp = (const float4*)(g_tab + xs * HC);
        #pragma unroll
        for (int j = 0; j < 4; j++) {
            float ev = __shfl_sync(0xffffffffu, ex, hj[j]);
            float4 v = fp[lane + 32 * j];
            acc[j].x += ev * v.x; acc[j].y += ev * v.y;
            acc[j].z += ev * v.z; acc[j].w += ev * v.w;
        }
    }

    float inv = (lane < H) ? 1.f / ssum : 0.f;
    float vals[16];
    float lsum = 0.f;
    #pragma unroll
    for (int j = 0; j < 4; j++) {
        float iv = __shfl_sync(0xffffffffu, inv, hj[j]);
        float4 b4 = ((const float4*)bias)[lane + 32 * j];
        vals[j * 4 + 0] = acc[j].x * iv + b4.x;
        vals[j * 4 + 1] = acc[j].y * iv + b4.y;
        vals[j * 4 + 2] = acc[j].z * iv + b4.z;
        vals[j * 4 + 3] = acc[j].w * iv + b4.w;
        lsum += vals[j * 4 + 0] + vals[j * 4 + 1] + vals[j * 4 + 2] + vals[j * 4 + 3];
    }
    #pragma unroll
    for (int o = 16; o; o >>= 1) lsum += __shfl_xor_sync(0xffffffffu, lsum, o);
    float mean = lsum * (1.f / HC);
    float lvar = 0.f;
    #pragma unroll
    for (int t = 0; t < 16; t++) { float d = vals[t] - mean; lvar += d * d; }
    #pragma unroll
    for (int o = 16; o; o >>= 1) lvar += __shfl_xor_sync(0xffffffffu, lvar, o);
    float rstd = rsqrtf(lvar * (1.f / HC) + EPS);

    float4* op = (float4*)(out + (size_t)node * HC);
    #pragma unroll
    for (int j = 0; j < 4; j++) {
        float4 gg = ((const float4*)gamma)[lane + 32 * j];
        float4 bb = ((const float4*)beta)[lane + 32 * j];
        float4 o4;
        float v;
        v = (vals[j * 4 + 0] - mean) * rstd * gg.x + bb.x; o4.x = v > 0.f ? v : __expf(v) - 1.f;
        v = (vals[j * 4 + 1] - mean) * rstd * gg.y + bb.y; o4.y = v > 0.f ? v : __expf(v) - 1.f;
        v = (vals[j * 4 + 2] - mean) * rstd * gg.z + bb.z; o4.z = v > 0.f ? v : __expf(v) - 1.f;
        v = (vals[j * 4 + 3] - mean) * rstd * gg.w + bb.w; o4.w = v > 0.f ? v : __expf(v) - 1.f;
        op[lane + 32 * j] = o4;
    }
}

// ---------------- fp32 SGEMM (layer 3): g_featB = g_featA @ W ----------------
__global__ __launch_bounds__(256) void k_sgemm_AB(const float* __restrict__ W, int M, int Nc, int K) {
    __shared__ float As[16][64];
    __shared__ float Bs[16][64];
    const float* A = g_featA;
    float* C = g_featB;
    int tid = threadIdx.x;
    int tx = tid & 15, ty = tid >> 4;
    int rowBase = blockIdx.x * 64;
    int colBase = blockIdx.y * 64;
    float acc[4][4] = {};
    for (int k0 = 0; k0 < K; k0 += 16) {
        {
            int r = tid >> 2, c4 = (tid & 3) << 2;
            int row = rowBase + r;
            float4 v = make_float4(0.f, 0.f, 0.f, 0.f);
            if (row < M) v = *(const float4*)(A + (size_t)row * K + k0 + c4);
            As[c4 + 0][r] = v.x; As[c4 + 1][r] = v.y;
            As[c4 + 2][r] = v.z; As[c4 + 3][r] = v.w;
        }
        {
            int k = tid >> 4, c4 = (tid & 15) << 2;
            int col = colBase + c4;
            float4 v = make_float4(0.f, 0.f, 0.f, 0.f);
            if (col < Nc) v = *(const float4*)(W + (size_t)(k0 + k) * Nc + col);
            *(float4*)&Bs[k][c4] = v;
        }
        __syncthreads();
        #pragma unroll
        for (int k = 0; k < 16; k++) {
            float a[4], b[4];
            #pragma unroll
            for (int i = 0; i < 4; i++) a[i] = As[k][ty * 4 + i];
            #pragma unroll
            for (int j = 0; j < 4; j++) b[j] = Bs[k][tx * 4 + j];
            #pragma unroll
            for (int i = 0; i < 4; i++)
                #pragma unroll
                for (int j = 0; j < 4; j++) acc[i][j] += a[i] * b[j];
        }
        __syncthreads();
    }
    #pragma unroll
    for (int i = 0; i < 4; i++) {
        int row = rowBase + ty * 4 + i;
        if (row < M) {
            #pragma unroll
            for (int j = 0; j < 4; j++) {
                int col = colBase + tx * 4 + j;
                if (col < Nc) C[(size_t)row * Nc + col] = acc[i][j];
            }
        }
    }
}

// ---------------- tf32 tensor-core GEMM (layer 2): g_featB = g_featA[M,512] @ W[512,512] ----
// Block tile 128x64, K-chunk 32. 8 warps, each 32x32 via mma.sync.m16n8k8 tf32.
// A/B staged into smem in FRAGMENT-MAJOR layout so mainloop fragment loads are
// a single LDS.128 (A) / LDS.64 (B) per tile — no ldmatrix needed.
__global__ __launch_bounds__(256) void k_mma_tf32(const float* __restrict__ W, int M) {
    __shared__ uint32_t Af[4 * 8 * 32 * 4];  // [kb][mt][thread][idx]  16KB
    __shared__ uint32_t Bf[4 * 8 * 32 * 2];  // [kb][nt][thread][idx]   8KB
    const float* A = g_featA;
    float* C = g_featB;
    int tid = threadIdx.x;
    int lane = tid & 31, wid = tid >> 5;
    int warpM = wid & 3, warpN = wid >> 2;     // 4 x 2 warp grid
    int rowBase = blockIdx.x * 128;
    int colBase = blockIdx.y * 64;

    float acc[2][4][4];
    #pragma unroll
    for (int i = 0; i < 2; i++)
        #pragma unroll
        for (int j = 0; j < 4; j++)
            #pragma unroll
            for (int q = 0; q < 4; q++) acc[i][j][q] = 0.f;

    for (int k0 = 0; k0 < 512; k0 += 32) {
        // ---- stage A tile (128 x 32) into fragment-major smem ----
        #pragma unroll
        for (int p = 0; p < 4; p++) {
            int r = p * 32 + (tid >> 3);
            int f = tid & 7;
            int row = rowBase + r;
            float4 v = make_float4(0.f, 0.f, 0.f, 0.f);
            if (row < M) v = *(const float4*)(A + (size_t)row * 512 + k0 + f * 4);
            int mt = r >> 4, rr = r & 15, g = rr & 7, half = rr >> 3;
            float vv[4] = {v.x, v.y, v.z, v.w};
            #pragma unroll
            for (int e = 0; e < 4; e++) {
                int kin = f * 4 + e;
                int tg = kin & 3, khalf = (kin >> 2) & 1, kb = kin >> 3;
                uint32_t tf;
                asm("cvt.rna.tf32.f32 %0, %1;" : "=r"(tf) : "f"(vv[e]));
                Af[(((kb * 8 + mt) * 32) + (g * 4 + tg)) * 4 + khalf * 2 + half] = tf;
            }
        }
        // ---- stage B tile (32 x 64) ----
        #pragma unroll
        for (int p = 0; p < 2; p++) {
            int kr = p * 16 + (tid >> 4);
            int nc4 = tid & 15;
            float4 v = *(const float4*)(W + (size_t)(k0 + kr) * 512 + colBase + nc4 * 4);
            int tg = kr & 3, khalf = (kr >> 2) & 1, kb = kr >> 3;
            float vv[4] = {v.x, v.y, v.z, v.w};
            #pragma unroll
            for (int e = 0; e < 4; e++) {
                int nn = nc4 * 4 + e;
                int nt = nn >> 3, g = nn & 7;
                uint32_t tf;
                asm("cvt.rna.tf32.f32 %0, %1;" : "=r"(tf) : "f"(vv[e]));
                Bf[(((kb * 8 + nt) * 32) + (g * 4 + tg)) * 2 + khalf] = tf;
            }
        }
        __syncthreads();
        // ---- 4 k-steps of m16n8k8 ----
        #pragma unroll
        for (int kb = 0; kb < 4; kb++) {
            uint32_t a[2][4], b[4][2];
            #pragma unroll
            for (int mt2 = 0; mt2 < 2; mt2++) {
                int mt = warpM * 2 + mt2;
                uint4 aa = *(const uint4*)&Af[((kb * 8 + mt) * 32 + lane) * 4];
                a[mt2][0] = aa.x; a[mt2][1] = aa.y; a[mt2][2] = aa.z; a[mt2][3] = aa.w;
            }
            #pragma unroll
            for (int nt2 = 0; nt2 < 4; nt2++) {
                int nt = warpN * 4 + nt2;
                uint2 bb = *(const uint2*)&Bf[((kb * 8 + nt) * 32 + lane) * 2];
                b[nt2][0] = bb.x; b[nt2][1] = bb.y;
            }
            #pragma unroll
            for (int mt2 = 0; mt2 < 2; mt2++)
                #pragma unroll
                for (int nt2 = 0; nt2 < 4; nt2++)
                    asm volatile(
                        "mma.sync.aligned.m16n8k8.row.col.f32.tf32.tf32.f32 "
                        "{%0,%1,%2,%3}, {%4,%5,%6,%7}, {%8,%9}, {%0,%1,%2,%3};"
                        : "+f"(acc[mt2][nt2][0]), "+f"(acc[mt2][nt2][1]),
                          "+f"(acc[mt2][nt2][2]), "+f"(acc[mt2][nt2][3])
                        : "r"(a[mt2][0]), "r"(a[mt2][1]), "r"(a[mt2][2]), "r"(a[mt2][3]),
                          "r"(b[nt2][0]), "r"(b[nt2][1]));
        }
        __syncthreads();
    }
    // ---- epilogue ----
    int g = lane >> 2, tg = lane & 3;
    #pragma unroll
    for (int mt2 = 0; mt2 < 2; mt2++) {
        int row0 = rowBase + warpM * 32 + mt2 * 16 + g;
        #pragma unroll
        for (int nt2 = 0; nt2 < 4; nt2++) {
            int col = colBase + warpN * 32 + nt2 * 8 + tg * 2;
            if (row0 < M)
                *(float2*)(C + (size_t)row0 * 512 + col) =
                    make_float2(acc[mt2][nt2][0], acc[mt2][nt2][1]);
            if (row0 + 8 < M)
                *(float2*)(C + (size_t)(row0 + 8) * 512 + col) =
                    make_float2(acc[mt2][nt2][2], acc[mt2][nt2][3]);
        }
    }
}

// ---------------- attention coefficients: al/ar per (node, head) ----------------
template <int H, int C>
__global__ void k_coef(const float* __restrict__ a_src, const float* __restrict__ a_dst, int n) {
    int gw = (blockIdx.x * blockDim.x + threadIdx.x) >> 5;
    int lane = threadIdx.x & 31;
    if (gw >= n * H) return;
    int node = gw / H, h = gw % H;
    const float* f = g_featB + (size_t)node * (H * C) + h * C;
    float sa = 0.f, sd = 0.f;
    #pragma unroll
    for (int c = lane; c < C; c += 32) {
        float v = f[c];
        sa += v * a_src[h * C + c];
        sd += v * a_dst[h * C + c];
    }
    #pragma unroll
    for (int o = 16; o; o >>= 1) {
        sa += __shfl_xor_sync(0xffffffffu, sa, o);
        sd += __shfl_xor_sync(0xffffffffu, sd, o);
    }
    if (lane == 0) { g_al[node * H + h] = sa; g_ar[node * H + h] = sd; }
}

// ---------------- GAT aggregation for HC=512 layers, fused bias+LN+ELU ----------------
// Edge loop manually unrolled x2 for memory-level parallelism (exact same
// accumulation ORDER as the rolled loop — bit-identical results).
template <int H, int C>
__global__ __launch_bounds__(256) void k_agg512(const float* __restrict__ bias,
                                                const float* __restrict__ gamma,
                                                const float* __restrict__ beta,
                                                int n) {
    constexpr int HC = H * C;  // 512
    int warp = (blockIdx.x * blockDim.x + threadIdx.x) >> 5;
    int lane = threadIdx.x & 31;
    if (warp >= n) return;
    int node = warp;
    const float* feat = g_featB;
    float* out = g_featA;

    int hj[4];
    #pragma unroll
    for (int j = 0; j < 4; j++) hj[j] = (4 * lane + 128 * j) / C;

    float arv = 0.f, alself = 0.f;
    if (lane < H) {
        arv = g_ar[node * H + lane];
        alself = g_al[node * H + lane];
    }
    float m = -3.4e38f;
    if (lane < H) m = leaky02(alself + arv);

    int beg = g_rowptr[node], end = g_rowptr[node + 1];
    // pass 1: per-head max (pairwise; fmax chain order preserved)
    {
        int k = beg;
        for (; k + 1 < end; k += 2) {
            int s0 = g_csrsrc[k], s1 = g_csrsrc[k + 1];
            float a0 = (lane < H) ? g_al[s0 * H + lane] : 0.f;
            float a1 = (lane < H) ? g_al[s1 * H + lane] : 0.f;
            if (lane < H) {
                m = fmaxf(m, leaky02(a0 + arv));
                m = fmaxf(m, leaky02(a1 + arv));
            }
        }
        if (k < end) {
            int s = g_csrsrc[k];
            float a = (lane < H) ? g_al[s * H + lane] : 0.f;
            if (lane < H) m = fmaxf(m, leaky02(a + arv));
        }
    }

    // pass 2: sum of exp + weighted feature accumulation (self-loop first)
    float ssum = 0.f;
    float4 acc[4];
    #pragma unroll
    for (int j = 0; j < 4; j++) acc[j] = make_float4(0.f, 0.f, 0.f, 0.f);

    {
        float ex = (lane < H) ? __expf(leaky02(alself + arv) - m) : 0.f;
        ssum += ex;
        const float4* fp = (const float4*)(feat + (size_t)node * HC);
        #pragma unroll
        for (int j = 0; j < 4; j++) {
            float ev = __shfl_sync(0xffffffffu, ex, hj[j]);
            float4 v = fp[lane + 32 * j];
            acc[j].x += ev * v.x; acc[j].y += ev * v.y;
            acc[j].z += ev * v.z; acc[j].w += ev * v.w;
        }
    }
    {
        int k = beg;
        for (; k + 1 < end; k += 2) {
            int s0 = g_csrsrc[k], s1 = g_csrsrc[k + 1];
            float a0 = (lane < H) ? g_al[s0 * H + lane] : 0.f;
            float a1 = (lane < H) ? g_al[s1 * H + lane] : 0.f;
            float ex0 = (lane < H) ? __expf(leaky02(a0 + arv) - m) : 0.f;
            float ex1 = (lane < H) ? __expf(leaky02(a1 + arv) - m) : 0.f;
            ssum += ex0;
            ssum += ex1;
            const float4* fp0 = (const float4*)(feat + (size_t)s0 * HC);
            const float4* fp1 = (const float4*)(feat + (size_t)s1 * HC);
            float4 v0[4], v1[4];
            #pragma unroll
            for (int j = 0; j < 4; j++) v0[j] = fp0[lane + 32 * j];
            #pragma unroll
            for (int j = 0; j < 4; j++) v1[j] = fp1[lane + 32 * j];
            // accumulate edge0 fully, then edge1 — same order as rolled loop
            #pragma unroll
            for (int j = 0; j < 4; j++) {
                float ev = __shfl_sync(0xffffffffu, ex0, hj[j]);
                acc[j].x += ev * v0[j].x; acc[j].y += ev * v0[j].y;
                acc[j].z += ev * v0[j].z; acc[j].w += ev * v0[j].w;
            }
            #pragma unroll
            for (int j = 0; j < 4; j++) {
                float ev = __shfl_sync(0xffffffffu, ex1, hj[j]);
                acc[j].x += ev * v1[j].x; acc[j].y += ev * v1[j].y;
                acc[j].z += ev * v1[j].z; acc[j].w += ev * v1[j].w;
            }
        }
        if (k < end) {
            int s = g_csrsrc[k];
            float a = (lane < H) ? g_al[s * H + lane] : 0.f;
            float ex = (lane < H) ? __expf(leaky02(a + arv) - m) : 0.f;
            ssum += ex;
            const float4* fp = (const float4*)(feat + (size_t)s * HC);
            #pragma unroll
            for (int j = 0; j < 4; j++) {
                float ev = __shfl_sync(0xffffffffu, ex, hj[j]);
                float4 v = fp[lane + 32 * j];
                acc[j].x += ev * v.x; acc[j].y += ev * v.y;
                acc[j].z += ev * v.z; acc[j].w += ev * v.w;
            }
        }
    }

    float inv = (lane < H) ? 1.f / ssum : 0.f;
    float vals[16];
    float lsum = 0.f;
    #pragma unroll
    for (int j = 0; j < 4; j++) {
        float iv = __shfl_sync(0xffffffffu, inv, hj[j]);
        float4 b4 = ((const float4*)bias)[lane + 32 * j];
        vals[j * 4 + 0] = acc[j].x * iv + b4.x;
        vals[j * 4 + 1] = acc[j].y * iv + b4.y;
        vals[j * 4 + 2] = acc[j].z * iv + b4.z;
        vals[j * 4 + 3] = acc[j].w * iv + b4.w;
        lsum += vals[j * 4 + 0] + vals[j * 4 + 1] + vals[j * 4 + 2] + vals[j * 4 + 3];
    }
    #pragma unroll
    for (int o = 16; o; o >>= 1) lsum += __shfl_xor_sync(0xffffffffu, lsum, o);
    float mean = lsum * (1.f / HC);
    float lvar = 0.f;
    #pragma unroll
    for (int t = 0; t < 16; t++) { float d = vals[t] - mean; lvar += d * d; }
    #pragma unroll
    for (int o = 16; o; o >>= 1) lvar += __shfl_xor_sync(0xffffffffu, lvar, o);
    float rstd = rsqrtf(lvar * (1.f / HC) + EPS);

    float4* op = (float4*)(out + (size_t)node * HC);
    #pragma unroll
    for (int j = 0; j < 4; j++) {
        float4 gg = ((const float4*)gamma)[lane + 32 * j];
        float4 bb = ((const float4*)beta)[lane + 32 * j];
        float4 o4;
        float v;
        v = (vals[j * 4 + 0] - mean) * rstd * gg.x + bb.x; o4.x = v > 0.f ? v : __expf(v) - 1.f;
        v = (vals[j * 4 + 1] - mean) * rstd * gg.y + bb.y; o4.y = v > 0.f ? v : __expf(v) - 1.f;
        v = (vals[j * 4 + 2] - mean) * rstd * gg.z + bb.z; o4.z = v > 0.f ? v : __expf(v) - 1.f;
        v = (vals[j * 4 + 3] - mean) * rstd * gg.w + bb.w; o4.w = v > 0.f ? v : __expf(v) - 1.f;
        op[lane + 32 * j] = o4;
    }
}

// ---------------- layer-3 aggregation (H=1, C=16), fused bias+LN+ELU+pool ----------------
__global__ __launch_bounds__(256) void k_agg3(const float* __restrict__ b3,
                                              const float* __restrict__ g3,
                                              const float* __restrict__ be3,
                                              const int* __restrict__ batch, int n) {
    int warp = (blockIdx.x * blockDim.x + threadIdx.x) >> 5;
    int lane = threadIdx.x & 31;
    if (warp >= n) return;
    int node = warp;
    const float* feat = g_featB;

    float arv = g_ar[node];
    float alself = g_al[node];
    float m = leaky02(alself + arv);
    int beg = g_rowptr[node], end = g_rowptr[node + 1];
    for (int k = beg; k < end; k++) {
        int s = g_csrsrc[k];
        m = fmaxf(m, leaky02(g_al[s] + arv));
    }
    float ssum = __expf(leaky02(alself + arv) - m);
    float acc = (lane < 16) ? ssum * feat[(size_t)node * 16 + lane] : 0.f;
    for (int k = beg; k < end; k++) {
        int s = g_csrsrc[k];
        float ex = __expf(leaky02(g_al[s] + arv) - m);
        ssum += ex;
        if (lane < 16) acc += ex * feat[(size_t)s * 16 + lane];
    }
    if (lane < 16) {
        float val = acc / ssum + b3[lane];
        float t = val;
        #pragma unroll
        for (int o = 8; o; o >>= 1) t += __shfl_xor_sync(0x0000ffffu, t, o);
        float mean = t * (1.f / 16.f);
        float d = val - mean;
        float v2 = d * d;
        #pragma unroll
        for (int o = 8; o; o >>= 1) v2 += __shfl_xor_sync(0x0000ffffu, v2, o);
        float rstd = rsqrtf(v2 * (1.f / 16.f) + EPS);
        float o_ = d * rstd * g3[lane] + be3[lane];
        o_ = o_ > 0.f ? o_ : __expf(o_) - 1.f;
        int g = batch[node];
        atomicAdd(&g_pool[g * 16 + lane], o_);
        if (lane == 0) atomicAdd(&g_cnt[g], 1.f);
    }
}

// ---------------- final mean-pool + MLP ----------------
__global__ void k_final(const float* __restrict__ fcW1, const float* __restrict__ fcb1,
                        const float* __restrict__ fcW2, const float* __restrict__ fcb2,
                        float* __restrict__ out) {
    __shared__ float pooled[GGRP][16];
    __shared__ float hid[GGRP][16];
    int t = threadIdx.x;
    if (t < GGRP * 16) {
        int g = t >> 4, c = t & 15;
        pooled[g][c] = g_pool[g * 16 + c] / fmaxf(g_cnt[g], 1.f);
    }
    __syncthreads();
    if (t < GGRP * 16) {
        int g = t >> 4, i = t & 15;
        float s = fcb1[i];
        #pragma unroll
        for (int j = 0; j < 16; j++) s += pooled[g][j] * fcW1[j * 16 + i];
        hid[g][i] = fmaxf(s, 0.f);
    }
    __syncthreads();
    if (t < GGRP * 8) {
        int g = t >> 3, k = t & 7;
        float s = fcb2[k];
        #pragma unroll
        for (int j = 0; j < 16; j++) s += hid[g][j] * fcW2[j * 8 + k];
        out[g * 8 + k] = s;
    }
}

// ---------------- launch ----------------
extern "C" void kernel_launch(void* const* d_in, const int* in_sizes, int n_in,
                              void* d_out, int out_size) {
    const int*   x      = (const int*)d_in[0];
    const int*   ei     = (const int*)d_in[1];
    const int*   batch  = (const int*)d_in[2];
    const float* emb    = (const float*)d_in[3];
    const float* W1     = (const float*)d_in[4];
    const float* a_src1 = (const float*)d_in[5];
    const float* a_dst1 = (const float*)d_in[6];
    const float* b1     = (const float*)d_in[7];
    const float* g1     = (const float*)d_in[8];
    const float* be1    = (const float*)d_in[9];
    const float* W2     = (const float*)d_in[10];
    const float* a_src2 = (const float*)d_in[11];
    const float* a_dst2 = (const float*)d_in[12];
    const float* b2     = (const float*)d_in[13];
    const float* g2     = (const float*)d_in[14];
    const float* be2    = (const float*)d_in[15];
    const float* W3     = (const float*)d_in[16];
    const float* a_src3 = (const float*)d_in[17];
    const float* a_dst3 = (const float*)d_in[18];
    const float* b3     = (const float*)d_in[19];
    const float* g3     = (const float*)d_in[20];
    const float* be3    = (const float*)d_in[21];
    const float* fcW1   = (const float*)d_in[22];
    const float* fcb1   = (const float*)d_in[23];
    const float* fcW2   = (const float*)d_in[24];
    const float* fcb2   = (const float*)d_in[25];

    int n = in_sizes[0];
    int e = in_sizes[1] / 2;
    const int* src = ei;
    const int* dst = ei + e;

    // init + CSR build
    k_init<<<(n + 255) / 256, 256>>>(n);
    k_count<<<(e + 255) / 256, 256>>>(dst, e);
    k_scan<<<1, 1024>>>(n);
    k_scatter<<<(e + 255) / 256, 256>>>(src, dst, e);

    int aggBlocks = (n * 32 + 255) / 256;

    // layer 1: 16 -> 512 (H=8, C=64). Input has only 32 distinct rows: the GEMM
    // collapses to a 32x512 table; aggregation reads the table DIRECTLY via x[]
    // (all L1-resident) — no materialized featB, no al/ar gather.
    {
        k_table<<<TILE, 512>>>(emb, W1);
        k_tabcoef<<<TILE, 256>>>(a_src1, a_dst1);
        k_agg1<<<aggBlocks, 256>>>(x, b1, g1, be1, n);
    }
    // layer 2: 512 -> 512 (H=4, C=128), tf32 tensor-core GEMM
    {
        dim3 grid((n + 127) / 128, 512 / 64);
        k_mma_tf32<<<grid, 256>>>(W2, n);
        k_coef<4, 128><<<(n * 4 * 32 + 255) / 256, 256>>>(a_src2, a_dst2, n);
        k_agg512<4, 128><<<aggBlocks, 256>>>(b2, g2, be2, n);
    }
    // layer 3: 512 -> 16 (H=1, C=16), fp32 GEMM
    {
        dim3 grid((n + 63) / 64, 1);
        k_sgemm_AB<<<grid, 256>>>(W3, n, 16, 512);
        k_coef<1, 16><<<(n * 32 + 255) / 256, 256>>>(a_src3, a_dst3, n);
        k_agg3<<<aggBlocks, 256>>>(b3, g3, be3, batch, n);
    }
    // pool + MLP
    k_final<<<1, 800>>>(fcW1, fcb1, fcW2, fcb2, (float*)d_out);
}